// round 15
// baseline (speedup 1.0000x reference)
#include <cuda_runtime.h>
#include <math.h>
#include <stdint.h>

#define D 128
#define ES 20
#define FCUT 5.0f
#define NT 16      // nodes per block (node kernels)
#define CH 64      // edges per staging chunk (aggregate kernel)
#define MAXN 20000
#define MAXE 600000
#define AGG_BLOCKS 1184   // persistent grid

// ---- device scratch (static, no allocs) ----
__device__ float g_so[MAXN * 384];          // scalar_output
__device__ int   g_cnt[MAXN];               // per-dst degree
__device__ int   g_loc[MAXN];               // block-local inclusive scan
__device__ int   g_bsum[32];                // per-block sums
__device__ int   g_rowoff[MAXN + 1];        // CSR offsets
__device__ int   g_rank[MAXE];              // per-edge rank within dst
__device__ int   g_src[MAXE];               // CSR-ordered src
__device__ int   g_eid[MAXE];               // CSR-ordered original edge id
__device__ float g_fc[MAXE];                // CSR-ordered cutoff weight

__device__ __forceinline__ float silu_f(float x) {
    return x / (1.0f + __expf(-x));
}

__device__ __forceinline__ void cp_async16(void* smem, const void* gmem) {
    unsigned int s = (unsigned int)__cvta_generic_to_shared(smem);
    asm volatile("cp.async.ca.shared.global [%0], [%1], 16;" :: "r"(s), "l"(gmem) : "memory");
}
__device__ __forceinline__ void cp_async4(void* smem, const void* gmem) {
    unsigned int s = (unsigned int)__cvta_generic_to_shared(smem);
    asm volatile("cp.async.ca.shared.global [%0], [%1], 4;" :: "r"(s), "l"(gmem) : "memory");
}
__device__ __forceinline__ void cp_commit() {
    asm volatile("cp.async.commit_group;" ::: "memory");
}
template<int N> __device__ __forceinline__ void cp_wait() {
    asm volatile("cp.async.wait_group %0;" :: "n"(N) : "memory");
}

// ---------------------------------------------------------------------------
// CSR build: zero -> hist(rank) -> scan_local -> scan_finalize -> scatter
// ---------------------------------------------------------------------------
__global__ void zero_kernel(int n) {
    int i = blockIdx.x * blockDim.x + threadIdx.x;
    if (i < n) g_cnt[i] = 0;
}

__global__ void hist_kernel(const int* __restrict__ edge_index, int nE) {
    int e = blockIdx.x * blockDim.x + threadIdx.x;
    if (e < nE) g_rank[e] = atomicAdd(&g_cnt[edge_index[2 * e + 1]], 1);
}

__global__ __launch_bounds__(1024) void scan_local_kernel(int n) {
    __shared__ int sh[1024];
    const int b = blockIdx.x, t = threadIdx.x;
    const int i = b * 1024 + t;
    int v = (i < n) ? g_cnt[i] : 0;
    sh[t] = v;
    __syncthreads();
    #pragma unroll
    for (int off = 1; off < 1024; off <<= 1) {
        int x = sh[t];
        int y = (t >= off) ? sh[t - off] : 0;
        __syncthreads();
        sh[t] = x + y;
        __syncthreads();
    }
    if (i < n) g_loc[i] = sh[t];
    if (t == 1023) g_bsum[b] = sh[1023];
}

__global__ void scan_finalize_kernel(int n, int nb) {
    __shared__ int pre[32];
    const int t = threadIdx.x;
    if (t < 32) {
        int v = (t < nb) ? g_bsum[t] : 0;
        #pragma unroll
        for (int off = 1; off < 32; off <<= 1) {
            int y = __shfl_up_sync(0xffffffffu, v, off);
            if (t >= off) v += y;
        }
        pre[t] = v;
    }
    __syncthreads();
    int i = blockIdx.x * blockDim.x + t;
    if (i == 0) g_rowoff[0] = 0;
    if (i < n) {
        int b = i >> 10;
        int off = (b > 0) ? pre[b - 1] : 0;
        g_rowoff[i + 1] = off + g_loc[i];
    }
}

__global__ void scatter_kernel(
    const float* __restrict__ edge_norms,
    const int*   __restrict__ edge_index,
    int nE)
{
    int e = blockIdx.x * blockDim.x + threadIdx.x;
    if (e >= nE) return;
    int dst = edge_index[2 * e + 1];
    int pos = g_rowoff[dst] + g_rank[e];
    g_src[pos] = edge_index[2 * e];
    g_eid[pos] = e;
    float nr = edge_norms[e];
    g_fc[pos] = (nr < FCUT) ? 0.5f * (cospif(nr * (1.0f / FCUT)) + 1.0f) : 0.f;
}

// ---------------------------------------------------------------------------
// Kernel A: scalar_output = silu(s @ Wm1 + bm1) @ Wm2 + bm2   -> g_so[n][384]
// ---------------------------------------------------------------------------
__global__ __launch_bounds__(256) void node_mlp_kernel(
    const float* __restrict__ s_in,
    const float* __restrict__ Wm1, const float* __restrict__ bm1,
    const float* __restrict__ Wm2, const float* __restrict__ bm2,
    int n)
{
    __shared__ float s_s[NT * D];
    __shared__ float h_s[NT * D];
    const int t  = threadIdx.x;
    const int n0 = blockIdx.x * NT;
    const int rg = t >> 5;          // 0..7: nodes rg*2, rg*2+1
    const int cq = (t & 31) * 4;

    for (int i = t; i < NT * D; i += 256) {
        int nl = i >> 7;
        s_s[i] = (n0 + nl < n) ? s_in[(size_t)(n0 + nl) * D + (i & 127)] : 0.f;
    }
    __syncthreads();

    float acc[2][4];
    {
        float4 b = *(const float4*)&bm1[cq];
        #pragma unroll
        for (int i = 0; i < 2; i++) { acc[i][0]=b.x; acc[i][1]=b.y; acc[i][2]=b.z; acc[i][3]=b.w; }
    }
    #pragma unroll 4
    for (int k = 0; k < D; k++) {
        float4 w = *(const float4*)&Wm1[k * D + cq];
        #pragma unroll
        for (int i = 0; i < 2; i++) {
            float sv = s_s[(rg * 2 + i) * D + k];
            acc[i][0] += sv * w.x; acc[i][1] += sv * w.y;
            acc[i][2] += sv * w.z; acc[i][3] += sv * w.w;
        }
    }
    #pragma unroll
    for (int i = 0; i < 2; i++)
        #pragma unroll
        for (int j = 0; j < 4; j++)
            h_s[(rg * 2 + i) * D + cq + j] = silu_f(acc[i][j]);
    __syncthreads();

    float acc2[2][12];
    #pragma unroll
    for (int g = 0; g < 3; g++) {
        float4 b = *(const float4*)&bm2[g * D + cq];
        #pragma unroll
        for (int i = 0; i < 2; i++) {
            acc2[i][g*4+0]=b.x; acc2[i][g*4+1]=b.y; acc2[i][g*4+2]=b.z; acc2[i][g*4+3]=b.w;
        }
    }
    #pragma unroll 2
    for (int k = 0; k < D; k++) {
        float4 w0 = *(const float4*)&Wm2[k * 384 + cq];
        float4 w1 = *(const float4*)&Wm2[k * 384 + 128 + cq];
        float4 w2 = *(const float4*)&Wm2[k * 384 + 256 + cq];
        #pragma unroll
        for (int i = 0; i < 2; i++) {
            float hv = h_s[(rg * 2 + i) * D + k];
            acc2[i][0] += hv * w0.x; acc2[i][1]  += hv * w0.y;
            acc2[i][2] += hv * w0.z; acc2[i][3]  += hv * w0.w;
            acc2[i][4] += hv * w1.x; acc2[i][5]  += hv * w1.y;
            acc2[i][6] += hv * w1.z; acc2[i][7]  += hv * w1.w;
            acc2[i][8] += hv * w2.x; acc2[i][9]  += hv * w2.y;
            acc2[i][10]+= hv * w2.z; acc2[i][11] += hv * w2.w;
        }
    }
    #pragma unroll
    for (int i = 0; i < 2; i++) {
        int node = n0 + rg * 2 + i;
        if (node < n) {
            #pragma unroll
            for (int g = 0; g < 3; g++)
                *(float4*)&g_so[(size_t)node * 384 + g * D + cq] =
                    make_float4(acc2[i][g*4+0], acc2[i][g*4+1], acc2[i][g*4+2], acc2[i][g*4+3]);
        }
    }
}

// ---------------------------------------------------------------------------
// Kernel B: persistent node-centric aggregation, double-buffered cp.async,
// batch-4 gather groups (validated fastest inner-loop form).
// ---------------------------------------------------------------------------
struct AggState {
    float wf0[ES], wf1[ES], wf2[ES];
    float bf0, bf1, bf2v;
    float acc_s, av0, av1, av2;
};

__device__ __forceinline__ void agg_edge(
    AggState& st, int el,
    const float so0, const float so1, const float so2,
    const float vv0, const float vv1, const float vv2,
    const float fc, const float* es_s, const float* ev_s)
{
    float fw0 = st.bf0, fw1 = st.bf1, fw2 = st.bf2v;
    #pragma unroll
    for (int k = 0; k < ES; k++) {
        const float esk = es_s[el * ES + k];
        fw0 = fmaf(esk, st.wf0[k], fw0);
        fw1 = fmaf(esk, st.wf1[k], fw1);
        fw2 = fmaf(esk, st.wf2[k], fw2);
    }
    const float gn = fw0 * fc * so0;
    const float ge = fw1 * fc * so1;
    st.acc_s = fmaf(fw2 * fc, so2, st.acc_s);
    const float e0 = ev_s[el * 3 + 0], e1 = ev_s[el * 3 + 1], e2 = ev_s[el * 3 + 2];
    st.av0 = fmaf(vv0, gn, fmaf(ge, e0, st.av0));
    st.av1 = fmaf(vv1, gn, fmaf(ge, e1, st.av1));
    st.av2 = fmaf(vv2, gn, fmaf(ge, e2, st.av2));
}

__device__ __forceinline__ void stage_chunk(
    int base, int m, int t,
    const float* __restrict__ edge_states,
    const float* __restrict__ edge_vectors,
    float* es_s, float* ev_s, float* fc_s, int* src_s)
{
    for (int idx = t; idx < m * 5; idx += 128) {
        int el = idx / 5, q = idx - el * 5;
        int eid = g_eid[base + el];
        cp_async16(&es_s[el * ES + q * 4], &edge_states[(size_t)eid * ES + q * 4]);
    }
    for (int idx = t; idx < m * 3; idx += 128) {
        int el = idx / 3, a = idx - el * 3;
        int eid = g_eid[base + el];
        cp_async4(&ev_s[idx], &edge_vectors[(size_t)eid * 3 + a]);
    }
    if (t < m) {
        cp_async4(&src_s[t], &g_src[base + t]);
        cp_async4(&fc_s[t],  &g_fc[base + t]);
    }
}

template<bool FULL>
__device__ __forceinline__ void compute_chunk(
    AggState& st, int m, int t,
    const float* __restrict__ v_in,
    const float* es_s, const float* ev_s, const float* fc_s, const int* src_s)
{
    int el = 0;
    for (; el + 4 <= (FULL ? CH : m); el += 4) {
        const int s0 = src_s[el], s1 = src_s[el+1], s2 = src_s[el+2], s3 = src_s[el+3];
        const float* p0 = g_so + (size_t)s0 * 384;
        const float* p1 = g_so + (size_t)s1 * 384;
        const float* p2 = g_so + (size_t)s2 * 384;
        const float* p3 = g_so + (size_t)s3 * 384;
        const float* q0 = v_in + (size_t)s0 * 384;
        const float* q1 = v_in + (size_t)s1 * 384;
        const float* q2 = v_in + (size_t)s2 * 384;
        const float* q3 = v_in + (size_t)s3 * 384;
        float a00 = p0[t], a01 = p0[128+t], a02 = p0[256+t];
        float a10 = p1[t], a11 = p1[128+t], a12 = p1[256+t];
        float a20 = p2[t], a21 = p2[128+t], a22 = p2[256+t];
        float a30 = p3[t], a31 = p3[128+t], a32 = p3[256+t];
        float b00 = q0[t], b01 = q0[128+t], b02 = q0[256+t];
        float b10 = q1[t], b11 = q1[128+t], b12 = q1[256+t];
        float b20 = q2[t], b21 = q2[128+t], b22 = q2[256+t];
        float b30 = q3[t], b31 = q3[128+t], b32 = q3[256+t];
        agg_edge(st, el+0, a00,a01,a02, b00,b01,b02, fc_s[el+0], es_s, ev_s);
        agg_edge(st, el+1, a10,a11,a12, b10,b11,b12, fc_s[el+1], es_s, ev_s);
        agg_edge(st, el+2, a20,a21,a22, b20,b21,b22, fc_s[el+2], es_s, ev_s);
        agg_edge(st, el+3, a30,a31,a32, b30,b31,b32, fc_s[el+3], es_s, ev_s);
    }
    for (; el < (FULL ? CH : m); el++) {
        const int src = src_s[el];
        const float* sop = g_so + (size_t)src * 384;
        const float* vp  = v_in + (size_t)src * 384;
        agg_edge(st, el, sop[t], sop[128+t], sop[256+t],
                 vp[t], vp[128+t], vp[256+t], fc_s[el], es_s, ev_s);
    }
}

__global__ __launch_bounds__(128) void aggregate_kernel(
    const float* __restrict__ s_in,
    const float* __restrict__ v_in,
    const float* __restrict__ edge_states,
    const float* __restrict__ edge_vectors,
    const float* __restrict__ Wf, const float* __restrict__ bf,
    float* __restrict__ out_s, float* __restrict__ out_v,
    int n)
{
    const int t = threadIdx.x;

    AggState st;      // weights loaded once per block
    #pragma unroll
    for (int k = 0; k < ES; k++) {
        st.wf0[k] = Wf[k * 384 + t];
        st.wf1[k] = Wf[k * 384 + 128 + t];
        st.wf2[k] = Wf[k * 384 + 256 + t];
    }
    st.bf0 = bf[t]; st.bf1 = bf[128 + t]; st.bf2v = bf[256 + t];

    __shared__ __align__(16) float es_s[2][CH * ES];
    __shared__ float ev_s[2][CH * 3];
    __shared__ float fc_s[2][CH];
    __shared__ int   src_s[2][CH];

    for (int j = blockIdx.x; j < n; j += gridDim.x) {
        st.acc_s = s_in[(size_t)j * D + t];
        st.av0   = v_in[(size_t)j * 384 + t];
        st.av1   = v_in[(size_t)j * 384 + 128 + t];
        st.av2   = v_in[(size_t)j * 384 + 256 + t];

        const int start = g_rowoff[j];
        const int end   = g_rowoff[j + 1];
        const int nch   = (end - start + CH - 1) / CH;

        if (nch > 0) {
            stage_chunk(start, min(CH, end - start), t, edge_states, edge_vectors,
                        es_s[0], ev_s[0], fc_s[0], src_s[0]);
            cp_commit();
        }
        for (int c = 0; c < nch; c++) {
            const int b = c & 1;
            const int cbase = start + c * CH;
            const int m = min(CH, end - cbase);
            if (c + 1 < nch) {
                const int nbase = start + (c + 1) * CH;
                stage_chunk(nbase, min(CH, end - nbase), t, edge_states, edge_vectors,
                            es_s[b ^ 1], ev_s[b ^ 1], fc_s[b ^ 1], src_s[b ^ 1]);
                cp_commit();
                cp_wait<1>();
            } else {
                cp_wait<0>();
            }
            __syncthreads();
            if (m == CH)
                compute_chunk<true>(st, CH, t, v_in, es_s[b], ev_s[b], fc_s[b], src_s[b]);
            else
                compute_chunk<false>(st, m, t, v_in, es_s[b], ev_s[b], fc_s[b], src_s[b]);
            __syncthreads();
        }

        out_s[(size_t)j * D + t]         = st.acc_s;
        out_v[(size_t)j * 384 + t]       = st.av0;
        out_v[(size_t)j * 384 + 128 + t] = st.av1;
        out_v[(size_t)j * 384 + 256 + t] = st.av2;
    }
}

// ---------------------------------------------------------------------------
// Kernel C: node update; h aliases vvsq buffer; smem 72KB -> 3 blocks/SM.
// ---------------------------------------------------------------------------
__global__ __launch_bounds__(128, 3) void node_update_kernel(
    const float* __restrict__ WU, const float* __restrict__ WV,
    const float* __restrict__ Wa1, const float* __restrict__ ba1,
    const float* __restrict__ Wa2, const float* __restrict__ ba2,
    float* __restrict__ out_s, float* __restrict__ out_v,
    int n)
{
    extern __shared__ float sm[];
    float* s_s    = sm;                 // NT*128
    float* v_s    = s_s    + NT * 128;  // NT*384
    float* Uv_s   = v_s    + NT * 384;  // NT*384
    float* vvsq_s = Uv_s   + NT * 384;  // NT*128  (reused as h after hacc)
    float* ip_s   = vvsq_s + NT * 128;  // NT*128
    float* h_s    = vvsq_s;             // alias: vvsq dead once hacc computed

    const int t  = threadIdx.x;
    const int n0 = blockIdx.x * NT;
    const int rg = t >> 5;
    const int cq = (t & 31) * 4;

    for (int i = t; i < NT * 128; i += 128) {
        int nl = i >> 7;
        s_s[i] = (n0 + nl < n) ? out_s[(size_t)(n0 + nl) * D + (i & 127)] : 0.f;
    }
    for (int i = t; i < NT * 384; i += 128) {
        int nl = i / 384;
        v_s[i] = (n0 + nl < n) ? out_v[(size_t)(n0 + nl) * 384 + (i % 384)] : 0.f;
    }
    __syncthreads();

    float accU[12][4], accV[12][4];
    #pragma unroll
    for (int r = 0; r < 12; r++)
        #pragma unroll
        for (int j = 0; j < 4; j++) { accU[r][j] = 0.f; accV[r][j] = 0.f; }

    #pragma unroll 2
    for (int k = 0; k < D; k++) {
        float4 wu = *(const float4*)&WU[k * D + cq];
        float4 wv = *(const float4*)&WV[k * D + cq];
        #pragma unroll
        for (int r = 0; r < 12; r++) {
            float vv = v_s[(rg * 12 + r) * D + k];
            accU[r][0] += vv * wu.x; accU[r][1] += vv * wu.y;
            accU[r][2] += vv * wu.z; accU[r][3] += vv * wu.w;
            accV[r][0] += vv * wv.x; accV[r][1] += vv * wv.y;
            accV[r][2] += vv * wv.z; accV[r][3] += vv * wv.w;
        }
    }

    #pragma unroll
    for (int nl = 0; nl < 4; nl++) {
        float q[4] = {0.f, 0.f, 0.f, 0.f};
        float p[4] = {0.f, 0.f, 0.f, 0.f};
        #pragma unroll
        for (int a = 0; a < 3; a++) {
            int r = nl * 3 + a;
            #pragma unroll
            for (int j = 0; j < 4; j++) {
                q[j] += accV[r][j] * accV[r][j];
                p[j] += accU[r][j] * accV[r][j];
                Uv_s[(rg * 12 + r) * D + cq + j] = accU[r][j];
            }
        }
        #pragma unroll
        for (int j = 0; j < 4; j++) {
            vvsq_s[(rg * 4 + nl) * D + cq + j] = q[j];
            ip_s[(rg * 4 + nl) * D + cq + j]   = p[j];
        }
    }
    __syncthreads();

    float hacc[4][4];
    {
        float4 b = *(const float4*)&ba1[cq];
        #pragma unroll
        for (int i = 0; i < 4; i++) { hacc[i][0]=b.x; hacc[i][1]=b.y; hacc[i][2]=b.z; hacc[i][3]=b.w; }
    }
    #pragma unroll 2
    for (int k = 0; k < D; k++) {
        float4 w = *(const float4*)&Wa1[k * D + cq];
        #pragma unroll
        for (int i = 0; i < 4; i++) {
            float sv = s_s[(rg * 4 + i) * D + k];
            hacc[i][0] += sv * w.x; hacc[i][1] += sv * w.y;
            hacc[i][2] += sv * w.z; hacc[i][3] += sv * w.w;
        }
    }
    #pragma unroll 2
    for (int k = 0; k < D; k++) {
        float4 w = *(const float4*)&Wa1[(D + k) * D + cq];
        #pragma unroll
        for (int i = 0; i < 4; i++) {
            float qv = vvsq_s[(rg * 4 + i) * D + k];
            hacc[i][0] += qv * w.x; hacc[i][1] += qv * w.y;
            hacc[i][2] += qv * w.z; hacc[i][3] += qv * w.w;
        }
    }
    __syncthreads();   // all vvsq reads done before h overwrites the buffer
    #pragma unroll
    for (int i = 0; i < 4; i++)
        #pragma unroll
        for (int j = 0; j < 4; j++)
            h_s[(rg * 4 + i) * D + cq + j] = silu_f(hacc[i][j]);
    __syncthreads();

    float aacc[4][12];
    #pragma unroll
    for (int g = 0; g < 3; g++) {
        float4 b = *(const float4*)&ba2[g * D + cq];
        #pragma unroll
        for (int i = 0; i < 4; i++) {
            aacc[i][g*4+0]=b.x; aacc[i][g*4+1]=b.y; aacc[i][g*4+2]=b.z; aacc[i][g*4+3]=b.w;
        }
    }
    #pragma unroll 2
    for (int k = 0; k < D; k++) {
        float4 w0 = *(const float4*)&Wa2[k * 384 + cq];
        float4 w1 = *(const float4*)&Wa2[k * 384 + 128 + cq];
        float4 w2 = *(const float4*)&Wa2[k * 384 + 256 + cq];
        #pragma unroll
        for (int i = 0; i < 4; i++) {
            float hv = h_s[(rg * 4 + i) * D + k];
            aacc[i][0] += hv * w0.x; aacc[i][1]  += hv * w0.y;
            aacc[i][2] += hv * w0.z; aacc[i][3]  += hv * w0.w;
            aacc[i][4] += hv * w1.x; aacc[i][5]  += hv * w1.y;
            aacc[i][6] += hv * w1.z; aacc[i][7]  += hv * w1.w;
            aacc[i][8] += hv * w2.x; aacc[i][9]  += hv * w2.y;
            aacc[i][10]+= hv * w2.z; aacc[i][11] += hv * w2.w;
        }
    }

    #pragma unroll
    for (int i = 0; i < 4; i++) {
        const int nl = rg * 4 + i;
        const int node = n0 + nl;
        if (node >= n) continue;
        float4 os;
        const float* sp  = &s_s[nl * D + cq];
        const float* ipp = &ip_s[nl * D + cq];
        os.x = sp[0] + aacc[i][0] + aacc[i][4] * ipp[0];
        os.y = sp[1] + aacc[i][1] + aacc[i][5] * ipp[1];
        os.z = sp[2] + aacc[i][2] + aacc[i][6] * ipp[2];
        os.w = sp[3] + aacc[i][3] + aacc[i][7] * ipp[3];
        *(float4*)&out_s[(size_t)node * D + cq] = os;
        #pragma unroll
        for (int a = 0; a < 3; a++) {
            const int r = rg * 12 + i * 3 + a;
            const float* vp = &v_s[r * D + cq];
            const float* up = &Uv_s[r * D + cq];
            float4 ov;
            ov.x = vp[0] + aacc[i][8]  * up[0];
            ov.y = vp[1] + aacc[i][9]  * up[1];
            ov.z = vp[2] + aacc[i][10] * up[2];
            ov.w = vp[3] + aacc[i][11] * up[3];
            *(float4*)&out_v[(size_t)node * 384 + a * D + cq] = ov;
        }
    }
}

// ---------------------------------------------------------------------------
extern "C" void kernel_launch(void* const* d_in, const int* in_sizes, int n_in,
                              void* d_out, int out_size)
{
    const float* s_in  = (const float*)d_in[0];
    const float* v_in  = (const float*)d_in[1];
    const float* e_st  = (const float*)d_in[2];
    const float* e_vec = (const float*)d_in[3];
    const float* e_nrm = (const float*)d_in[4];
    const int*   e_idx = (const int*)  d_in[5];
    const float* Wf  = (const float*)d_in[6];
    const float* bf  = (const float*)d_in[7];
    const float* Wm1 = (const float*)d_in[8];
    const float* bm1 = (const float*)d_in[9];
    const float* Wm2 = (const float*)d_in[10];
    const float* bm2 = (const float*)d_in[11];
    const float* WU  = (const float*)d_in[12];
    const float* WV  = (const float*)d_in[13];
    const float* Wa1 = (const float*)d_in[14];
    const float* ba1 = (const float*)d_in[15];
    const float* Wa2 = (const float*)d_in[16];
    const float* ba2 = (const float*)d_in[17];

    const int n  = in_sizes[0] / D;
    const int nE = in_sizes[2] / ES;
    const int nb = (n + 1023) / 1024;

    float* out_s = (float*)d_out;
    float* out_v = out_s + (size_t)n * D;

    // lazily-created side stream + events (first call = correctness run, not captured)
    static cudaStream_t s2 = nullptr;
    static cudaEvent_t ev_fork = nullptr, ev_join = nullptr;
    if (s2 == nullptr) {
        cudaStreamCreateWithFlags(&s2, cudaStreamNonBlocking);
        cudaEventCreateWithFlags(&ev_fork, cudaEventDisableTiming);
        cudaEventCreateWithFlags(&ev_join, cudaEventDisableTiming);
    }

    // s, v, Uv, vvsq(=h), ip  ->  16 * 1152 floats = 72KB
    const size_t smem_c = (size_t)NT * (128 + 384 + 384 + 128 + 128) * sizeof(float);
    cudaFuncSetAttribute(node_update_kernel,
                         cudaFuncAttributeMaxDynamicSharedMemorySize, (int)smem_c);

    // fork: node_mlp on s2, CSR chain on main stream (independent work)
    cudaEventRecord(ev_fork, 0);
    cudaStreamWaitEvent(s2, ev_fork, 0);
    node_mlp_kernel<<<(n + NT - 1) / NT, 256, 0, s2>>>(s_in, Wm1, bm1, Wm2, bm2, n);
    cudaEventRecord(ev_join, s2);

    zero_kernel<<<(n + 255) / 256, 256>>>(n);
    hist_kernel<<<(nE + 255) / 256, 256>>>(e_idx, nE);
    scan_local_kernel<<<nb, 1024>>>(n);
    scan_finalize_kernel<<<(n + 255) / 256, 256>>>(n, nb);
    scatter_kernel<<<(nE + 255) / 256, 256>>>(e_nrm, e_idx, nE);

    // join: aggregate needs both CSR and g_so
    cudaStreamWaitEvent(0, ev_join, 0);

    // persistent node-centric message aggregation (writes s+ds, v+dv directly)
    const int agg_grid = (n < AGG_BLOCKS) ? n : AGG_BLOCKS;
    aggregate_kernel<<<agg_grid, 128>>>(s_in, v_in, e_st, e_vec, Wf, bf, out_s, out_v, n);

    // final node update
    node_update_kernel<<<(n + NT - 1) / NT, 128, smem_c>>>(WU, WV, Wa1, ba1, Wa2, ba2,
                                                           out_s, out_v, n);
}

// round 16
// speedup vs baseline: 1.2143x; 1.2143x over previous
#include <cuda_runtime.h>
#include <math.h>
#include <stdint.h>

#define D 128
#define ES 20
#define FCUT 5.0f
#define NT 16      // nodes per block (node kernels)
#define CH 32      // edges per staging chunk (aggregate kernel)
#define MAXN 20000
#define MAXE 600000
#define AGG_BLOCKS 1184   // persistent grid

// ---- device scratch (static, no allocs) ----
__device__ float g_so[MAXN * 384];          // scalar_output
__device__ int   g_cnt[MAXN];               // per-dst degree
__device__ int   g_loc[MAXN];               // block-local inclusive scan
__device__ int   g_bsum[32];                // per-block sums
__device__ int   g_rowoff[MAXN + 1];        // CSR offsets
__device__ int   g_rank[MAXE];              // per-edge rank within dst
__device__ int   g_src[MAXE];               // CSR-ordered src
__device__ int   g_eid[MAXE];               // CSR-ordered original edge id
__device__ float g_fc[MAXE];                // CSR-ordered cutoff weight

__device__ __forceinline__ float silu_f(float x) {
    return x / (1.0f + __expf(-x));
}

__device__ __forceinline__ void cp_async16(void* smem, const void* gmem) {
    unsigned int s = (unsigned int)__cvta_generic_to_shared(smem);
    asm volatile("cp.async.ca.shared.global [%0], [%1], 16;" :: "r"(s), "l"(gmem) : "memory");
}
__device__ __forceinline__ void cp_async4(void* smem, const void* gmem) {
    unsigned int s = (unsigned int)__cvta_generic_to_shared(smem);
    asm volatile("cp.async.ca.shared.global [%0], [%1], 4;" :: "r"(s), "l"(gmem) : "memory");
}
__device__ __forceinline__ void cp_commit() {
    asm volatile("cp.async.commit_group;" ::: "memory");
}
template<int N> __device__ __forceinline__ void cp_wait() {
    asm volatile("cp.async.wait_group %0;" :: "n"(N) : "memory");
}

// ---------------------------------------------------------------------------
// CSR build: zero -> hist(rank) -> scan_local -> scan_finalize -> scatter
// ---------------------------------------------------------------------------
__global__ void zero_kernel(int n) {
    int i = blockIdx.x * blockDim.x + threadIdx.x;
    if (i < n) g_cnt[i] = 0;
}

__global__ void hist_kernel(const int* __restrict__ edge_index, int nE) {
    int e = blockIdx.x * blockDim.x + threadIdx.x;
    if (e < nE) g_rank[e] = atomicAdd(&g_cnt[edge_index[2 * e + 1]], 1);
}

__global__ __launch_bounds__(1024) void scan_local_kernel(int n) {
    __shared__ int sh[1024];
    const int b = blockIdx.x, t = threadIdx.x;
    const int i = b * 1024 + t;
    int v = (i < n) ? g_cnt[i] : 0;
    sh[t] = v;
    __syncthreads();
    #pragma unroll
    for (int off = 1; off < 1024; off <<= 1) {
        int x = sh[t];
        int y = (t >= off) ? sh[t - off] : 0;
        __syncthreads();
        sh[t] = x + y;
        __syncthreads();
    }
    if (i < n) g_loc[i] = sh[t];
    if (t == 1023) g_bsum[b] = sh[1023];
}

__global__ void scan_finalize_kernel(int n, int nb) {
    __shared__ int pre[32];
    const int t = threadIdx.x;
    if (t < 32) {
        int v = (t < nb) ? g_bsum[t] : 0;
        #pragma unroll
        for (int off = 1; off < 32; off <<= 1) {
            int y = __shfl_up_sync(0xffffffffu, v, off);
            if (t >= off) v += y;
        }
        pre[t] = v;
    }
    __syncthreads();
    int i = blockIdx.x * blockDim.x + t;
    if (i == 0) g_rowoff[0] = 0;
    if (i < n) {
        int b = i >> 10;
        int off = (b > 0) ? pre[b - 1] : 0;
        g_rowoff[i + 1] = off + g_loc[i];
    }
}

__global__ void scatter_kernel(
    const float* __restrict__ edge_norms,
    const int*   __restrict__ edge_index,
    int nE)
{
    int e = blockIdx.x * blockDim.x + threadIdx.x;
    if (e >= nE) return;
    int dst = edge_index[2 * e + 1];
    int pos = g_rowoff[dst] + g_rank[e];
    g_src[pos] = edge_index[2 * e];
    g_eid[pos] = e;
    float nr = edge_norms[e];
    g_fc[pos] = (nr < FCUT) ? 0.5f * (cospif(nr * (1.0f / FCUT)) + 1.0f) : 0.f;
}

// ---------------------------------------------------------------------------
// Kernel A: scalar_output = silu(s @ Wm1 + bm1) @ Wm2 + bm2   -> g_so[n][384]
// ---------------------------------------------------------------------------
__global__ __launch_bounds__(256) void node_mlp_kernel(
    const float* __restrict__ s_in,
    const float* __restrict__ Wm1, const float* __restrict__ bm1,
    const float* __restrict__ Wm2, const float* __restrict__ bm2,
    int n)
{
    __shared__ float s_s[NT * D];
    __shared__ float h_s[NT * D];
    const int t  = threadIdx.x;
    const int n0 = blockIdx.x * NT;
    const int rg = t >> 5;          // 0..7: nodes rg*2, rg*2+1
    const int cq = (t & 31) * 4;

    for (int i = t; i < NT * D; i += 256) {
        int nl = i >> 7;
        s_s[i] = (n0 + nl < n) ? s_in[(size_t)(n0 + nl) * D + (i & 127)] : 0.f;
    }
    __syncthreads();

    float acc[2][4];
    {
        float4 b = *(const float4*)&bm1[cq];
        #pragma unroll
        for (int i = 0; i < 2; i++) { acc[i][0]=b.x; acc[i][1]=b.y; acc[i][2]=b.z; acc[i][3]=b.w; }
    }
    #pragma unroll 4
    for (int k = 0; k < D; k++) {
        float4 w = *(const float4*)&Wm1[k * D + cq];
        #pragma unroll
        for (int i = 0; i < 2; i++) {
            float sv = s_s[(rg * 2 + i) * D + k];
            acc[i][0] += sv * w.x; acc[i][1] += sv * w.y;
            acc[i][2] += sv * w.z; acc[i][3] += sv * w.w;
        }
    }
    #pragma unroll
    for (int i = 0; i < 2; i++)
        #pragma unroll
        for (int j = 0; j < 4; j++)
            h_s[(rg * 2 + i) * D + cq + j] = silu_f(acc[i][j]);
    __syncthreads();

    float acc2[2][12];
    #pragma unroll
    for (int g = 0; g < 3; g++) {
        float4 b = *(const float4*)&bm2[g * D + cq];
        #pragma unroll
        for (int i = 0; i < 2; i++) {
            acc2[i][g*4+0]=b.x; acc2[i][g*4+1]=b.y; acc2[i][g*4+2]=b.z; acc2[i][g*4+3]=b.w;
        }
    }
    #pragma unroll 2
    for (int k = 0; k < D; k++) {
        float4 w0 = *(const float4*)&Wm2[k * 384 + cq];
        float4 w1 = *(const float4*)&Wm2[k * 384 + 128 + cq];
        float4 w2 = *(const float4*)&Wm2[k * 384 + 256 + cq];
        #pragma unroll
        for (int i = 0; i < 2; i++) {
            float hv = h_s[(rg * 2 + i) * D + k];
            acc2[i][0] += hv * w0.x; acc2[i][1]  += hv * w0.y;
            acc2[i][2] += hv * w0.z; acc2[i][3]  += hv * w0.w;
            acc2[i][4] += hv * w1.x; acc2[i][5]  += hv * w1.y;
            acc2[i][6] += hv * w1.z; acc2[i][7]  += hv * w1.w;
            acc2[i][8] += hv * w2.x; acc2[i][9]  += hv * w2.y;
            acc2[i][10]+= hv * w2.z; acc2[i][11] += hv * w2.w;
        }
    }
    #pragma unroll
    for (int i = 0; i < 2; i++) {
        int node = n0 + rg * 2 + i;
        if (node < n) {
            #pragma unroll
            for (int g = 0; g < 3; g++)
                *(float4*)&g_so[(size_t)node * 384 + g * D + cq] =
                    make_float4(acc2[i][g*4+0], acc2[i][g*4+1], acc2[i][g*4+2], acc2[i][g*4+3]);
        }
    }
}

// ---------------------------------------------------------------------------
// Kernel B: persistent node-centric aggregation, double-buffered cp.async,
// batch-4 gather groups; es multiplier loads via explicit LDS.128.
// ---------------------------------------------------------------------------
struct AggState {
    float wf0[ES], wf1[ES], wf2[ES];
    float bf0, bf1, bf2v;
    float acc_s, av0, av1, av2;
};

__device__ __forceinline__ void agg_edge(
    AggState& st, int el,
    const float so0, const float so1, const float so2,
    const float vv0, const float vv1, const float vv2,
    const float fc, const float* es_s, const float* ev_s)
{
    float fw0 = st.bf0, fw1 = st.bf1, fw2 = st.bf2v;
    // es row is 80B, 16B-aligned -> 5 LDS.128 broadcasts instead of 20 LDS.32
    const float4* e4 = (const float4*)(es_s + el * ES);
    #pragma unroll
    for (int q = 0; q < ES / 4; q++) {
        const float4 e = e4[q];
        fw0 = fmaf(e.x, st.wf0[4*q+0], fw0);
        fw1 = fmaf(e.x, st.wf1[4*q+0], fw1);
        fw2 = fmaf(e.x, st.wf2[4*q+0], fw2);
        fw0 = fmaf(e.y, st.wf0[4*q+1], fw0);
        fw1 = fmaf(e.y, st.wf1[4*q+1], fw1);
        fw2 = fmaf(e.y, st.wf2[4*q+1], fw2);
        fw0 = fmaf(e.z, st.wf0[4*q+2], fw0);
        fw1 = fmaf(e.z, st.wf1[4*q+2], fw1);
        fw2 = fmaf(e.z, st.wf2[4*q+2], fw2);
        fw0 = fmaf(e.w, st.wf0[4*q+3], fw0);
        fw1 = fmaf(e.w, st.wf1[4*q+3], fw1);
        fw2 = fmaf(e.w, st.wf2[4*q+3], fw2);
    }
    const float gn = fw0 * fc * so0;
    const float ge = fw1 * fc * so1;
    st.acc_s = fmaf(fw2 * fc, so2, st.acc_s);
    const float e0 = ev_s[el * 3 + 0], e1 = ev_s[el * 3 + 1], e2 = ev_s[el * 3 + 2];
    st.av0 = fmaf(vv0, gn, fmaf(ge, e0, st.av0));
    st.av1 = fmaf(vv1, gn, fmaf(ge, e1, st.av1));
    st.av2 = fmaf(vv2, gn, fmaf(ge, e2, st.av2));
}

__device__ __forceinline__ void stage_chunk(
    int base, int m, int t,
    const float* __restrict__ edge_states,
    const float* __restrict__ edge_vectors,
    float* es_s, float* ev_s, float* fc_s, int* src_s)
{
    for (int idx = t; idx < m * 5; idx += 128) {
        int el = idx / 5, q = idx - el * 5;
        int eid = g_eid[base + el];
        cp_async16(&es_s[el * ES + q * 4], &edge_states[(size_t)eid * ES + q * 4]);
    }
    if (t < m * 3) {
        int el = t / 3, a = t - el * 3;
        int eid = g_eid[base + el];
        cp_async4(&ev_s[t], &edge_vectors[(size_t)eid * 3 + a]);
    }
    if (t < m) {
        cp_async4(&src_s[t], &g_src[base + t]);
        cp_async4(&fc_s[t],  &g_fc[base + t]);
    }
}

template<bool FULL>
__device__ __forceinline__ void compute_chunk(
    AggState& st, int m, int t,
    const float* __restrict__ v_in,
    const float* es_s, const float* ev_s, const float* fc_s, const int* src_s)
{
    int el = 0;
    for (; el + 4 <= (FULL ? CH : m); el += 4) {
        const int s0 = src_s[el], s1 = src_s[el+1], s2 = src_s[el+2], s3 = src_s[el+3];
        const float* p0 = g_so + (size_t)s0 * 384;
        const float* p1 = g_so + (size_t)s1 * 384;
        const float* p2 = g_so + (size_t)s2 * 384;
        const float* p3 = g_so + (size_t)s3 * 384;
        const float* q0 = v_in + (size_t)s0 * 384;
        const float* q1 = v_in + (size_t)s1 * 384;
        const float* q2 = v_in + (size_t)s2 * 384;
        const float* q3 = v_in + (size_t)s3 * 384;
        float a00 = p0[t], a01 = p0[128+t], a02 = p0[256+t];
        float a10 = p1[t], a11 = p1[128+t], a12 = p1[256+t];
        float a20 = p2[t], a21 = p2[128+t], a22 = p2[256+t];
        float a30 = p3[t], a31 = p3[128+t], a32 = p3[256+t];
        float b00 = q0[t], b01 = q0[128+t], b02 = q0[256+t];
        float b10 = q1[t], b11 = q1[128+t], b12 = q1[256+t];
        float b20 = q2[t], b21 = q2[128+t], b22 = q2[256+t];
        float b30 = q3[t], b31 = q3[128+t], b32 = q3[256+t];
        agg_edge(st, el+0, a00,a01,a02, b00,b01,b02, fc_s[el+0], es_s, ev_s);
        agg_edge(st, el+1, a10,a11,a12, b10,b11,b12, fc_s[el+1], es_s, ev_s);
        agg_edge(st, el+2, a20,a21,a22, b20,b21,b22, fc_s[el+2], es_s, ev_s);
        agg_edge(st, el+3, a30,a31,a32, b30,b31,b32, fc_s[el+3], es_s, ev_s);
    }
    for (; el < (FULL ? CH : m); el++) {
        const int src = src_s[el];
        const float* sop = g_so + (size_t)src * 384;
        const float* vp  = v_in + (size_t)src * 384;
        agg_edge(st, el, sop[t], sop[128+t], sop[256+t],
                 vp[t], vp[128+t], vp[256+t], fc_s[el], es_s, ev_s);
    }
}

__global__ __launch_bounds__(128) void aggregate_kernel(
    const float* __restrict__ s_in,
    const float* __restrict__ v_in,
    const float* __restrict__ edge_states,
    const float* __restrict__ edge_vectors,
    const float* __restrict__ Wf, const float* __restrict__ bf,
    float* __restrict__ out_s, float* __restrict__ out_v,
    int n)
{
    const int t = threadIdx.x;

    AggState st;      // weights loaded once per block
    #pragma unroll
    for (int k = 0; k < ES; k++) {
        st.wf0[k] = Wf[k * 384 + t];
        st.wf1[k] = Wf[k * 384 + 128 + t];
        st.wf2[k] = Wf[k * 384 + 256 + t];
    }
    st.bf0 = bf[t]; st.bf1 = bf[128 + t]; st.bf2v = bf[256 + t];

    __shared__ __align__(16) float es_s[2][CH * ES];
    __shared__ float ev_s[2][CH * 3];
    __shared__ float fc_s[2][CH];
    __shared__ int   src_s[2][CH];

    for (int j = blockIdx.x; j < n; j += gridDim.x) {
        st.acc_s = s_in[(size_t)j * D + t];
        st.av0   = v_in[(size_t)j * 384 + t];
        st.av1   = v_in[(size_t)j * 384 + 128 + t];
        st.av2   = v_in[(size_t)j * 384 + 256 + t];

        const int start = g_rowoff[j];
        const int end   = g_rowoff[j + 1];
        const int nch   = (end - start + CH - 1) / CH;

        if (nch > 0) {
            stage_chunk(start, min(CH, end - start), t, edge_states, edge_vectors,
                        es_s[0], ev_s[0], fc_s[0], src_s[0]);
            cp_commit();
        }
        for (int c = 0; c < nch; c++) {
            const int b = c & 1;
            const int cbase = start + c * CH;
            const int m = min(CH, end - cbase);
            if (c + 1 < nch) {
                const int nbase = start + (c + 1) * CH;
                stage_chunk(nbase, min(CH, end - nbase), t, edge_states, edge_vectors,
                            es_s[b ^ 1], ev_s[b ^ 1], fc_s[b ^ 1], src_s[b ^ 1]);
                cp_commit();
                cp_wait<1>();
            } else {
                cp_wait<0>();
            }
            __syncthreads();
            if (m == CH)
                compute_chunk<true>(st, CH, t, v_in, es_s[b], ev_s[b], fc_s[b], src_s[b]);
            else
                compute_chunk<false>(st, m, t, v_in, es_s[b], ev_s[b], fc_s[b], src_s[b]);
            __syncthreads();
        }

        out_s[(size_t)j * D + t]         = st.acc_s;
        out_v[(size_t)j * 384 + t]       = st.av0;
        out_v[(size_t)j * 384 + 128 + t] = st.av1;
        out_v[(size_t)j * 384 + 256 + t] = st.av2;
    }
}

// ---------------------------------------------------------------------------
// Kernel C: node update; h aliases vvsq buffer; smem 72KB -> 3 blocks/SM.
// ---------------------------------------------------------------------------
__global__ __launch_bounds__(128, 3) void node_update_kernel(
    const float* __restrict__ WU, const float* __restrict__ WV,
    const float* __restrict__ Wa1, const float* __restrict__ ba1,
    const float* __restrict__ Wa2, const float* __restrict__ ba2,
    float* __restrict__ out_s, float* __restrict__ out_v,
    int n)
{
    extern __shared__ float sm[];
    float* s_s    = sm;                 // NT*128
    float* v_s    = s_s    + NT * 128;  // NT*384
    float* Uv_s   = v_s    + NT * 384;  // NT*384
    float* vvsq_s = Uv_s   + NT * 384;  // NT*128  (reused as h after hacc)
    float* ip_s   = vvsq_s + NT * 128;  // NT*128
    float* h_s    = vvsq_s;             // alias: vvsq dead once hacc computed

    const int t  = threadIdx.x;
    const int n0 = blockIdx.x * NT;
    const int rg = t >> 5;
    const int cq = (t & 31) * 4;

    for (int i = t; i < NT * 128; i += 128) {
        int nl = i >> 7;
        s_s[i] = (n0 + nl < n) ? out_s[(size_t)(n0 + nl) * D + (i & 127)] : 0.f;
    }
    for (int i = t; i < NT * 384; i += 128) {
        int nl = i / 384;
        v_s[i] = (n0 + nl < n) ? out_v[(size_t)(n0 + nl) * 384 + (i % 384)] : 0.f;
    }
    __syncthreads();

    float accU[12][4], accV[12][4];
    #pragma unroll
    for (int r = 0; r < 12; r++)
        #pragma unroll
        for (int j = 0; j < 4; j++) { accU[r][j] = 0.f; accV[r][j] = 0.f; }

    #pragma unroll 2
    for (int k = 0; k < D; k++) {
        float4 wu = *(const float4*)&WU[k * D + cq];
        float4 wv = *(const float4*)&WV[k * D + cq];
        #pragma unroll
        for (int r = 0; r < 12; r++) {
            float vv = v_s[(rg * 12 + r) * D + k];
            accU[r][0] += vv * wu.x; accU[r][1] += vv * wu.y;
            accU[r][2] += vv * wu.z; accU[r][3] += vv * wu.w;
            accV[r][0] += vv * wv.x; accV[r][1] += vv * wv.y;
            accV[r][2] += vv * wv.z; accV[r][3] += vv * wv.w;
        }
    }

    #pragma unroll
    for (int nl = 0; nl < 4; nl++) {
        float q[4] = {0.f, 0.f, 0.f, 0.f};
        float p[4] = {0.f, 0.f, 0.f, 0.f};
        #pragma unroll
        for (int a = 0; a < 3; a++) {
            int r = nl * 3 + a;
            #pragma unroll
            for (int j = 0; j < 4; j++) {
                q[j] += accV[r][j] * accV[r][j];
                p[j] += accU[r][j] * accV[r][j];
                Uv_s[(rg * 12 + r) * D + cq + j] = accU[r][j];
            }
        }
        #pragma unroll
        for (int j = 0; j < 4; j++) {
            vvsq_s[(rg * 4 + nl) * D + cq + j] = q[j];
            ip_s[(rg * 4 + nl) * D + cq + j]   = p[j];
        }
    }
    __syncthreads();

    float hacc[4][4];
    {
        float4 b = *(const float4*)&ba1[cq];
        #pragma unroll
        for (int i = 0; i < 4; i++) { hacc[i][0]=b.x; hacc[i][1]=b.y; hacc[i][2]=b.z; hacc[i][3]=b.w; }
    }
    #pragma unroll 2
    for (int k = 0; k < D; k++) {
        float4 w = *(const float4*)&Wa1[k * D + cq];
        #pragma unroll
        for (int i = 0; i < 4; i++) {
            float sv = s_s[(rg * 4 + i) * D + k];
            hacc[i][0] += sv * w.x; hacc[i][1] += sv * w.y;
            hacc[i][2] += sv * w.z; hacc[i][3] += sv * w.w;
        }
    }
    #pragma unroll 2
    for (int k = 0; k < D; k++) {
        float4 w = *(const float4*)&Wa1[(D + k) * D + cq];
        #pragma unroll
        for (int i = 0; i < 4; i++) {
            float qv = vvsq_s[(rg * 4 + i) * D + k];
            hacc[i][0] += qv * w.x; hacc[i][1] += qv * w.y;
            hacc[i][2] += qv * w.z; hacc[i][3] += qv * w.w;
        }
    }
    __syncthreads();   // all vvsq reads done before h overwrites the buffer
    #pragma unroll
    for (int i = 0; i < 4; i++)
        #pragma unroll
        for (int j = 0; j < 4; j++)
            h_s[(rg * 4 + i) * D + cq + j] = silu_f(hacc[i][j]);
    __syncthreads();

    float aacc[4][12];
    #pragma unroll
    for (int g = 0; g < 3; g++) {
        float4 b = *(const float4*)&ba2[g * D + cq];
        #pragma unroll
        for (int i = 0; i < 4; i++) {
            aacc[i][g*4+0]=b.x; aacc[i][g*4+1]=b.y; aacc[i][g*4+2]=b.z; aacc[i][g*4+3]=b.w;
        }
    }
    #pragma unroll 2
    for (int k = 0; k < D; k++) {
        float4 w0 = *(const float4*)&Wa2[k * 384 + cq];
        float4 w1 = *(const float4*)&Wa2[k * 384 + 128 + cq];
        float4 w2 = *(const float4*)&Wa2[k * 384 + 256 + cq];
        #pragma unroll
        for (int i = 0; i < 4; i++) {
            float hv = h_s[(rg * 4 + i) * D + k];
            aacc[i][0] += hv * w0.x; aacc[i][1]  += hv * w0.y;
            aacc[i][2] += hv * w0.z; aacc[i][3]  += hv * w0.w;
            aacc[i][4] += hv * w1.x; aacc[i][5]  += hv * w1.y;
            aacc[i][6] += hv * w1.z; aacc[i][7]  += hv * w1.w;
            aacc[i][8] += hv * w2.x; aacc[i][9]  += hv * w2.y;
            aacc[i][10]+= hv * w2.z; aacc[i][11] += hv * w2.w;
        }
    }

    #pragma unroll
    for (int i = 0; i < 4; i++) {
        const int nl = rg * 4 + i;
        const int node = n0 + nl;
        if (node >= n) continue;
        float4 os;
        const float* sp  = &s_s[nl * D + cq];
        const float* ipp = &ip_s[nl * D + cq];
        os.x = sp[0] + aacc[i][0] + aacc[i][4] * ipp[0];
        os.y = sp[1] + aacc[i][1] + aacc[i][5] * ipp[1];
        os.z = sp[2] + aacc[i][2] + aacc[i][6] * ipp[2];
        os.w = sp[3] + aacc[i][3] + aacc[i][7] * ipp[3];
        *(float4*)&out_s[(size_t)node * D + cq] = os;
        #pragma unroll
        for (int a = 0; a < 3; a++) {
            const int r = rg * 12 + i * 3 + a;
            const float* vp = &v_s[r * D + cq];
            const float* up = &Uv_s[r * D + cq];
            float4 ov;
            ov.x = vp[0] + aacc[i][8]  * up[0];
            ov.y = vp[1] + aacc[i][9]  * up[1];
            ov.z = vp[2] + aacc[i][10] * up[2];
            ov.w = vp[3] + aacc[i][11] * up[3];
            *(float4*)&out_v[(size_t)node * 384 + a * D + cq] = ov;
        }
    }
}

// ---------------------------------------------------------------------------
extern "C" void kernel_launch(void* const* d_in, const int* in_sizes, int n_in,
                              void* d_out, int out_size)
{
    const float* s_in  = (const float*)d_in[0];
    const float* v_in  = (const float*)d_in[1];
    const float* e_st  = (const float*)d_in[2];
    const float* e_vec = (const float*)d_in[3];
    const float* e_nrm = (const float*)d_in[4];
    const int*   e_idx = (const int*)  d_in[5];
    const float* Wf  = (const float*)d_in[6];
    const float* bf  = (const float*)d_in[7];
    const float* Wm1 = (const float*)d_in[8];
    const float* bm1 = (const float*)d_in[9];
    const float* Wm2 = (const float*)d_in[10];
    const float* bm2 = (const float*)d_in[11];
    const float* WU  = (const float*)d_in[12];
    const float* WV  = (const float*)d_in[13];
    const float* Wa1 = (const float*)d_in[14];
    const float* ba1 = (const float*)d_in[15];
    const float* Wa2 = (const float*)d_in[16];
    const float* ba2 = (const float*)d_in[17];

    const int n  = in_sizes[0] / D;
    const int nE = in_sizes[2] / ES;
    const int nb = (n + 1023) / 1024;

    float* out_s = (float*)d_out;
    float* out_v = out_s + (size_t)n * D;

    // s, v, Uv, vvsq(=h), ip  ->  16 * 1152 floats = 72KB
    const size_t smem_c = (size_t)NT * (128 + 384 + 384 + 128 + 128) * sizeof(float);
    cudaFuncSetAttribute(node_update_kernel,
                         cudaFuncAttributeMaxDynamicSharedMemorySize, (int)smem_c);

    // CSR build
    zero_kernel<<<(n + 255) / 256, 256>>>(n);
    hist_kernel<<<(nE + 255) / 256, 256>>>(e_idx, nE);
    scan_local_kernel<<<nb, 1024>>>(n);
    scan_finalize_kernel<<<(n + 255) / 256, 256>>>(n, nb);
    scatter_kernel<<<(nE + 255) / 256, 256>>>(e_nrm, e_idx, nE);

    // scalar_output MLP
    node_mlp_kernel<<<(n + NT - 1) / NT, 256>>>(s_in, Wm1, bm1, Wm2, bm2, n);

    // persistent node-centric message aggregation (writes s+ds, v+dv directly)
    const int agg_grid = (n < AGG_BLOCKS) ? n : AGG_BLOCKS;
    aggregate_kernel<<<agg_grid, 128>>>(s_in, v_in, e_st, e_vec, Wf, bf, out_s, out_v, n);

    // final node update
    node_update_kernel<<<(n + NT - 1) / NT, 128, smem_c>>>(WU, WV, Wa1, ba1, Wa2, ba2,
                                                           out_s, out_v, n);
}